// round 16
// baseline (speedup 1.0000x reference)
#include <cuda_runtime.h>
#include <cuda_fp16.h>
#include <cuda_pipeline_primitives.h>
#include <mma.h>
#include <cstdint>

using namespace nvcuda;

#define N_NODES_MAX 100000
#define N_NODES_PAD 100096              // multiple of 256 (GEMM BM)
#define N_EDGES_MAX 1600000
#define IN_F  256
#define OUT_F 128
#define SCAN_CHUNK 1024
#define MAX_SCAN_BLOCKS ((N_NODES_MAX + SCAN_CHUNK - 1) / SCAN_CHUNK)   // 98

#define GEMM_BM 256
#define GEMM_KC 64
#define GEMM_NCHUNK (IN_F / GEMM_KC)    // 4
#define LDA_S 72                        // A smem leading dim (halves): 64 + 8 pad
#define LDE_S 20                        // epilogue staging leading dim (floats)

// double-buffered dynamic smem (bytes)
#define SA_BYTES (GEMM_BM * LDA_S * 2)          // 36864 per buffer
#define SB_BYTES (GEMM_KC * OUT_F * 2)          // 16384 per buffer
#define SMEM_RAW (2 * SA_BYTES + 2 * SB_BYTES)  // 106496

// ---------------- device scratch ----------------
__device__ __half2 g_h2[(size_t)N_NODES_MAX * (OUT_F / 2)];   // 25.6 MB h fp16
__device__ __half  g_x_h[(size_t)N_NODES_PAD * IN_F];         // 51.2 MB x fp16 (padded)
__device__ int   g_counts[N_NODES_MAX];
__device__ int   g_rowstart[N_NODES_MAX];
__device__ int   g_cursor[N_NODES_MAX];
__device__ int   g_sorted_src[N_EDGES_MAX];
__device__ float g_sorted_w[N_EDGES_MAX];
__device__ int   g_blocksums[MAX_SCAN_BLOCKS];
__device__ int   g_blockoffs[MAX_SCAN_BLOCKS];
__device__ __half g_w_h[IN_F * OUT_F];                        // w in fp16

__device__ __forceinline__ int clamp_idx(int v, int n) {
    v = v < 0 ? 0 : v;
    return v >= n ? n - 1 : v;
}

// ---------------- 0a) prep: w -> fp16 ---------------------------------------
__global__ __launch_bounds__(256) void prep_w_kernel(const float* __restrict__ w)
{
    int e = blockIdx.x * blockDim.x + threadIdx.x;
    if (e < IN_F * OUT_F) g_w_h[e] = __float2half_rn(w[e]);
}

// ---------------- 0b) prep: x -> fp16 (8 elems/thread, pad rows zeroed) -----
__global__ __launch_bounds__(256) void conv_x_kernel(const float* __restrict__ x, int M)
{
    const int idx = blockIdx.x * blockDim.x + threadIdx.x;      // one uint4 out
    const int total = N_NODES_PAD * IN_F / 8;
    if (idx >= total) return;
    const int base = idx * 8;
    const int row = base >> 8;                                  // /IN_F
    __half2 hv[4];
    if (row < M) {
        const float4 v0 = *reinterpret_cast<const float4*>(x + base);
        const float4 v1 = *reinterpret_cast<const float4*>(x + base + 4);
        hv[0] = __floats2half2_rn(v0.x, v0.y);
        hv[1] = __floats2half2_rn(v0.z, v0.w);
        hv[2] = __floats2half2_rn(v1.x, v1.y);
        hv[3] = __floats2half2_rn(v1.z, v1.w);
    } else {
        hv[0] = hv[1] = hv[2] = hv[3] = __floats2half2_rn(0.f, 0.f);
    }
    *reinterpret_cast<uint4*>(g_x_h + base) = *reinterpret_cast<uint4*>(hv);
}

// ------ 1) fp16 WMMA GEMM: CTA 256x128, warp 64x64, cp.async double-buffer --
__global__ __launch_bounds__(256, 1) void gemm_wmma_kernel(int M)
{
    extern __shared__ __align__(16) char smem_raw[];
    __half (*sA)[GEMM_BM][LDA_S] =
        reinterpret_cast<__half (*)[GEMM_BM][LDA_S]>(smem_raw);
    __half (*sB)[GEMM_KC][OUT_F] =
        reinterpret_cast<__half (*)[GEMM_KC][OUT_F]>(smem_raw + 2 * SA_BYTES);

    const int tid = threadIdx.x;
    const int wid = tid >> 5;
    const int lane = tid & 31;
    const int warp_m = wid & 3;       // rows warp_m*64
    const int warp_n = wid >> 2;      // cols warp_n*64
    const int block_row = blockIdx.x * GEMM_BM;   // always < N_NODES_PAD

    wmma::fragment<wmma::accumulator, 16, 16, 16, float> acc[4][4];
#pragma unroll
    for (int mi = 0; mi < 4; mi++)
#pragma unroll
        for (int ni = 0; ni < 4; ni++) wmma::fill_fragment(acc[mi][ni], 0.0f);

    // cp.async copy of one chunk into buffer `buf`
    auto issue_chunk = [&](int c, int buf) {
        const int k0 = c * GEMM_KC;
        // A: 256 rows x 64 halves = 2048 x 16B segments; 8 per thread
#pragma unroll
        for (int i = 0; i < 8; i++) {
            const int s = i * 256 + tid;
            const int r = s >> 3, q = s & 7;
            __pipeline_memcpy_async(
                &sA[buf][r][q * 8],
                g_x_h + (size_t)(block_row + r) * IN_F + k0 + q * 8,
                16);
        }
        // B: 64x128 halves = 1024 x 16B segments; 4 per thread (contiguous)
#pragma unroll
        for (int i = 0; i < 4; i++) {
            const int s = i * 256 + tid;
            __pipeline_memcpy_async(
                reinterpret_cast<char*>(&sB[buf][0][0]) + s * 16,
                reinterpret_cast<const char*>(g_w_h + k0 * OUT_F) + s * 16,
                16);
        }
        __pipeline_commit();
    };

    issue_chunk(0, 0);

    for (int c = 0; c < GEMM_NCHUNK; c++) {
        const int buf = c & 1;
        if (c + 1 < GEMM_NCHUNK) {
            issue_chunk(c + 1, (c + 1) & 1);
            __pipeline_wait_prior(1);     // chunk c complete
        } else {
            __pipeline_wait_prior(0);
        }
        __syncthreads();

#pragma unroll
        for (int kk = 0; kk < GEMM_KC; kk += 16) {
            wmma::fragment<wmma::matrix_a, 16, 16, 16, __half, wmma::row_major> a[4];
#pragma unroll
            for (int mi = 0; mi < 4; mi++)
                wmma::load_matrix_sync(a[mi], &sA[buf][warp_m * 64 + mi * 16][kk], LDA_S);
#pragma unroll
            for (int ni = 0; ni < 4; ni++) {
                wmma::fragment<wmma::matrix_b, 16, 16, 16, __half, wmma::row_major> bf;
                wmma::load_matrix_sync(bf, &sB[buf][kk][warp_n * 64 + ni * 16], OUT_F);
#pragma unroll
                for (int mi = 0; mi < 4; mi++)
                    wmma::mma_sync(acc[mi][ni], a[mi], bf, acc[mi][ni]);
            }
        }
        __syncthreads();   // done reading buf before it is overwritten next iter
    }

    // epilogue: stage fp32 accs through smem, emit fp16
    float* sE = reinterpret_cast<float*>(smem_raw) + wid * (16 * LDE_S);
#pragma unroll
    for (int mi = 0; mi < 4; mi++) {
#pragma unroll
        for (int ni = 0; ni < 4; ni++) {
            wmma::store_matrix_sync(sE, acc[mi][ni], LDE_S, wmma::mem_row_major);
            __syncwarp();
            const int r = lane >> 1;
            const int c0 = (lane & 1) * 8;
            const int row = block_row + warp_m * 64 + mi * 16 + r;
            if (row < M) {
                const float* s = sE + r * LDE_S + c0;
                __half2 hv[4];
                hv[0] = __floats2half2_rn(s[0], s[1]);
                hv[1] = __floats2half2_rn(s[2], s[3]);
                hv[2] = __floats2half2_rn(s[4], s[5]);
                hv[3] = __floats2half2_rn(s[6], s[7]);
                const int col = warp_n * 64 + ni * 16 + c0;
                *reinterpret_cast<float4*>(&g_h2[(size_t)row * (OUT_F / 2) + col / 2]) =
                    *reinterpret_cast<float4*>(hv);
            }
            __syncwarp();
        }
    }
}

// ---------------- 2) CSR build -----------------------------------------
__global__ void zero_counts_kernel(int n)
{
    int i = blockIdx.x * blockDim.x + threadIdx.x;
    if (i < n) g_counts[i] = 0;
}

__global__ void hist_kernel(const int* __restrict__ edst, int E, int n_nodes)
{
    int t = blockIdx.x * blockDim.x + threadIdx.x;
    int base = t * 4;
    if (base + 3 < E) {
        int4 d4 = *reinterpret_cast<const int4*>(edst + base);
        atomicAdd(&g_counts[clamp_idx(d4.x, n_nodes)], 1);
        atomicAdd(&g_counts[clamp_idx(d4.y, n_nodes)], 1);
        atomicAdd(&g_counts[clamp_idx(d4.z, n_nodes)], 1);
        atomicAdd(&g_counts[clamp_idx(d4.w, n_nodes)], 1);
    } else {
        for (int e = base; e < E; e++)
            atomicAdd(&g_counts[clamp_idx(edst[e], n_nodes)], 1);
    }
}

__global__ __launch_bounds__(1024) void scan_pass1(int n)
{
    __shared__ int warp_sums[32];
    const int tid = threadIdx.x;
    const int i = blockIdx.x * SCAN_CHUNK + tid;
    int v = (i < n) ? g_counts[i] : 0;
    int s = v;
#pragma unroll
    for (int off = 16; off > 0; off >>= 1) s += __shfl_down_sync(0xffffffffu, s, off);
    if ((tid & 31) == 0) warp_sums[tid >> 5] = s;
    __syncthreads();
    if (tid < 32) {
        int t = warp_sums[tid];
#pragma unroll
        for (int off = 16; off > 0; off >>= 1) t += __shfl_down_sync(0xffffffffu, t, off);
        if (tid == 0) g_blocksums[blockIdx.x] = t;
    }
}

__global__ __launch_bounds__(128) void scan_pass2(int nblocks)
{
    const int tid = threadIdx.x;
    int v = (tid < nblocks) ? g_blocksums[tid] : 0;
    int x = v;
#pragma unroll
    for (int off = 1; off < 32; off <<= 1) {
        int y = __shfl_up_sync(0xffffffffu, x, off);
        if ((tid & 31) >= off) x += y;
    }
    __shared__ int ws[4];
    if ((tid & 31) == 31) ws[tid >> 5] = x;
    __syncthreads();
    int add = 0;
    for (int wlt = 0; wlt < (tid >> 5); wlt++) add += ws[wlt];
    int incl = x + add;
    if (tid < nblocks) g_blockoffs[tid] = incl - v;
}

__global__ __launch_bounds__(1024) void scan_pass3(int n)
{
    __shared__ int warp_sums[32];
    const int tid = threadIdx.x;
    const int i = blockIdx.x * SCAN_CHUNK + tid;
    int v = (i < n) ? g_counts[i] : 0;
    int x = v;
#pragma unroll
    for (int off = 1; off < 32; off <<= 1) {
        int y = __shfl_up_sync(0xffffffffu, x, off);
        if ((tid & 31) >= off) x += y;
    }
    if ((tid & 31) == 31) warp_sums[tid >> 5] = x;
    __syncthreads();
    if (tid < 32) {
        int t = warp_sums[tid];
#pragma unroll
        for (int off = 1; off < 32; off <<= 1) {
            int y = __shfl_up_sync(0xffffffffu, t, off);
            if (tid >= off) t += y;
        }
        warp_sums[tid] = t;
    }
    __syncthreads();
    int warp_off = (tid >> 5) ? warp_sums[(tid >> 5) - 1] : 0;
    int excl = x - v + warp_off + g_blockoffs[blockIdx.x];
    if (i < n) {
        g_rowstart[i] = excl;
        g_cursor[i]   = excl;
    }
}

__global__ void fill_kernel(const int* __restrict__ esrc,
                            const int* __restrict__ edst,
                            const float* __restrict__ ew, int E, int n_nodes)
{
    int e = blockIdx.x * blockDim.x + threadIdx.x;
    if (e < E) {
        int d = clamp_idx(edst[e], n_nodes);
        int pos = atomicAdd(&g_cursor[d], 1);
        if (pos >= 0 && pos < N_EDGES_MAX) {
            g_sorted_src[pos] = clamp_idx(esrc[e], n_nodes);
            g_sorted_w[pos]   = ew[e];
        }
    }
}

// ------- 3) gather: warp/node, fp16 h rows (8B/lane/edge), unrolled x4 ------
__global__ __launch_bounds__(256) void gather_kernel(
    const float* __restrict__ b, float* __restrict__ out, int n_nodes)
{
    const int gtid = blockIdx.x * blockDim.x + threadIdx.x;
    const int node = gtid >> 5;
    const int lane = gtid & 31;
    if (node >= n_nodes) return;

    const int start = g_rowstart[node];
    const int cnt   = g_counts[node];
    const __half2* hbase = g_h2 + (size_t)lane * 2;

    float4 acc0 = make_float4(0.f, 0.f, 0.f, 0.f);
    float4 acc1 = make_float4(0.f, 0.f, 0.f, 0.f);

    int j = 0;
    for (; j + 4 <= cnt; j += 4) {
        const int   s0 = g_sorted_src[start + j + 0];
        const int   s1 = g_sorted_src[start + j + 1];
        const int   s2 = g_sorted_src[start + j + 2];
        const int   s3 = g_sorted_src[start + j + 3];
        const float w0 = g_sorted_w[start + j + 0];
        const float w1 = g_sorted_w[start + j + 1];
        const float w2 = g_sorted_w[start + j + 2];
        const float w3 = g_sorted_w[start + j + 3];
        const __half2* p0 = hbase + (size_t)s0 * (OUT_F / 2);
        const __half2* p1 = hbase + (size_t)s1 * (OUT_F / 2);
        const __half2* p2 = hbase + (size_t)s2 * (OUT_F / 2);
        const __half2* p3 = hbase + (size_t)s3 * (OUT_F / 2);
        float2 a, c;
        a = __half22float2(p0[0]); c = __half22float2(p0[1]);
        acc0.x += w0 * a.x; acc0.y += w0 * a.y; acc0.z += w0 * c.x; acc0.w += w0 * c.y;
        a = __half22float2(p1[0]); c = __half22float2(p1[1]);
        acc1.x += w1 * a.x; acc1.y += w1 * a.y; acc1.z += w1 * c.x; acc1.w += w1 * c.y;
        a = __half22float2(p2[0]); c = __half22float2(p2[1]);
        acc0.x += w2 * a.x; acc0.y += w2 * a.y; acc0.z += w2 * c.x; acc0.w += w2 * c.y;
        a = __half22float2(p3[0]); c = __half22float2(p3[1]);
        acc1.x += w3 * a.x; acc1.y += w3 * a.y; acc1.z += w3 * c.x; acc1.w += w3 * c.y;
    }
    for (; j < cnt; j++) {
        const int   s  = g_sorted_src[start + j];
        const float wt = g_sorted_w[start + j];
        const __half2* p = hbase + (size_t)s * (OUT_F / 2);
        float2 a = __half22float2(p[0]);
        float2 c = __half22float2(p[1]);
        acc0.x += wt * a.x; acc0.y += wt * a.y; acc0.z += wt * c.x; acc0.w += wt * c.y;
    }

    const float4 bb = reinterpret_cast<const float4*>(b)[lane];
    float4 r;
    r.x = acc0.x + acc1.x + bb.x;
    r.y = acc0.y + acc1.y + bb.y;
    r.z = acc0.z + acc1.z + bb.z;
    r.w = acc0.w + acc1.w + bb.w;
    reinterpret_cast<float4*>(out)[(size_t)node * 32 + lane] = r;
}

// ---------------------------- launch ---------------------------------------
extern "C" void kernel_launch(void* const* d_in, const int* in_sizes, int n_in,
                              void* d_out, int out_size)
{
    const float* x    = (const float*)d_in[0];
    const int*   esrc = (const int*)d_in[1];
    const int*   edst = (const int*)d_in[2];
    const float* ew   = (const float*)d_in[3];
    const float* w    = (const float*)d_in[4];
    const float* b    = (const float*)d_in[5];
    float*       out  = (float*)d_out;

    const int M = in_sizes[0] / IN_F;   // 100000
    const int E = in_sizes[1];          // 1600000
    const int nscan = (M + SCAN_CHUNK - 1) / SCAN_CHUNK;

    static cudaStream_t s_side = nullptr;
    static cudaEvent_t  e_fork = nullptr, e_join = nullptr;
    if (!s_side) {
        cudaStreamCreateWithFlags(&s_side, cudaStreamNonBlocking);
        cudaEventCreateWithFlags(&e_fork, cudaEventDisableTiming);
        cudaEventCreateWithFlags(&e_join, cudaEventDisableTiming);
        cudaFuncSetAttribute(gemm_wmma_kernel,
                             cudaFuncAttributeMaxDynamicSharedMemorySize, SMEM_RAW);
    }

    prep_w_kernel<<<(IN_F * OUT_F + 255) / 256, 256>>>(w);        // 0 (main)

    cudaEventRecord(e_fork, 0);
    cudaStreamWaitEvent(s_side, e_fork, 0);

    zero_counts_kernel<<<(M + 255) / 256, 256, 0, s_side>>>(M);   // 1 (side)
    conv_x_kernel<<<(N_NODES_PAD * IN_F / 8 + 255) / 256, 256>>>(x, M);  // 2 (main)

    gemm_wmma_kernel<<<N_NODES_PAD / GEMM_BM, 256, SMEM_RAW>>>(M);       // 3 (main)

    hist_kernel<<<((E + 3) / 4 + 255) / 256, 256, 0, s_side>>>(edst, E, M); // 4
    scan_pass1<<<nscan, 1024, 0, s_side>>>(M);                    // 5
    scan_pass2<<<1, 128, 0, s_side>>>(nscan);                     // 6
    scan_pass3<<<nscan, 1024, 0, s_side>>>(M);                    // 7
    fill_kernel<<<(E + 255) / 256, 256, 0, s_side>>>(esrc, edst, ew, E, M); // 8

    cudaEventRecord(e_join, s_side);
    cudaStreamWaitEvent(0, e_join, 0);

    gather_kernel<<<((M * 32) + 255) / 256, 256>>>(b, out, M);    // 9
}

// round 17
// speedup vs baseline: 1.3689x; 1.3689x over previous
#include <cuda_runtime.h>
#include <cuda_fp16.h>
#include <mma.h>
#include <cstdint>

using namespace nvcuda;

#define N_NODES_MAX 100000
#define N_EDGES_MAX 1600000
#define IN_F  256
#define OUT_F 128
#define SCAN_CHUNK 1024
#define MAX_SCAN_BLOCKS ((N_NODES_MAX + SCAN_CHUNK - 1) / SCAN_CHUNK)   // 98

#define GEMM_BM 256                     // CTA rows
#define GEMM_KC 64
#define GEMM_NCHUNK (IN_F / GEMM_KC)    // 4
#define LDA_S 72                        // A smem leading dim (halves): 64 + 8 pad
#define LDE_S 20                        // epilogue staging leading dim (floats)

// dynamic smem: B resident (full w) + single A buffer
#define SB_BYTES (IN_F * OUT_F * 2)             // 65536 (all of w)
#define SA_BYTES (GEMM_BM * LDA_S * 2)          // 36864
#define SMEM_RAW (SB_BYTES + SA_BYTES)          // 102400

// ---------------- device scratch ----------------
__device__ __half2 g_h2[(size_t)N_NODES_MAX * (OUT_F / 2)];   // 25.6 MB h fp16
__device__ int   g_counts[N_NODES_MAX];
__device__ int   g_rowstart[N_NODES_MAX];
__device__ int   g_cursor[N_NODES_MAX];
__device__ int   g_sorted_src[N_EDGES_MAX];
__device__ float g_sorted_w[N_EDGES_MAX];
__device__ int   g_blocksums[MAX_SCAN_BLOCKS];
__device__ int   g_blockoffs[MAX_SCAN_BLOCKS];
__device__ __half g_w_h[IN_F * OUT_F];                        // w in fp16

__device__ __forceinline__ int clamp_idx(int v, int n) {
    v = v < 0 ? 0 : v;
    return v >= n ? n - 1 : v;
}

// ---------------- 0) prep: w -> fp16 ----------------------------------------
__global__ __launch_bounds__(256) void prep_w_kernel(const float* __restrict__ w)
{
    int e = blockIdx.x * blockDim.x + threadIdx.x;
    if (e < IN_F * OUT_F) g_w_h[e] = __float2half_rn(w[e]);
}

// ------ 1) fp16 WMMA GEMM: CTA 256x128, warp 64x64, B smem-resident --------
// 256 threads = 8 warps (4 m-groups x 2 n-groups).
__global__ __launch_bounds__(256, 1) void gemm_wmma_kernel(const float* __restrict__ x, int M)
{
    extern __shared__ __align__(16) char smem_raw[];
    __half (*sB)[OUT_F] = reinterpret_cast<__half (*)[OUT_F]>(smem_raw);        // [256][128]
    __half (*sA)[LDA_S] = reinterpret_cast<__half (*)[LDA_S]>(smem_raw + SB_BYTES);

    const int tid = threadIdx.x;
    const int wid = tid >> 5;
    const int lane = tid & 31;
    const int warp_m = wid & 3;       // rows warp_m*64
    const int warp_n = wid >> 2;      // cols warp_n*64
    const int block_row = blockIdx.x * GEMM_BM;

    // load ALL of B (w fp16, 64 KB = 4096 uint4) once: 16 per thread
    {
        const uint4* src = reinterpret_cast<const uint4*>(g_w_h);
        uint4* dst = reinterpret_cast<uint4*>(&sB[0][0]);
#pragma unroll
        for (int i = 0; i < 16; i++) dst[tid + i * 256] = src[tid + i * 256];
    }

    wmma::fragment<wmma::accumulator, 16, 16, 16, float> acc[4][4];
#pragma unroll
    for (int mi = 0; mi < 4; mi++)
#pragma unroll
        for (int ni = 0; ni < 4; ni++) wmma::fill_fragment(acc[mi][ni], 0.0f);

    for (int c = 0; c < GEMM_NCHUNK; c++) {
        const int k0 = c * GEMM_KC;
        // A: 256 rows x 64 floats = 4096 float4; 16 per thread (inline fp16 cvt)
#pragma unroll
        for (int i = 0; i < 16; i++) {
            const int idx = i * 256 + tid;
            const int r = idx >> 4, q = idx & 15;
            const int row = block_row + r;
            float4 v = make_float4(0.f, 0.f, 0.f, 0.f);
            if (row < M)
                v = *reinterpret_cast<const float4*>(x + (size_t)row * IN_F + k0 + q * 4);
            __half2* dst = reinterpret_cast<__half2*>(&sA[r][q * 4]);
            dst[0] = __floats2half2_rn(v.x, v.y);
            dst[1] = __floats2half2_rn(v.z, v.w);
        }
        __syncthreads();

#pragma unroll
        for (int kk = 0; kk < GEMM_KC; kk += 16) {
            wmma::fragment<wmma::matrix_a, 16, 16, 16, __half, wmma::row_major> a[4];
#pragma unroll
            for (int mi = 0; mi < 4; mi++)
                wmma::load_matrix_sync(a[mi], &sA[warp_m * 64 + mi * 16][kk], LDA_S);
#pragma unroll
            for (int ni = 0; ni < 4; ni++) {
                wmma::fragment<wmma::matrix_b, 16, 16, 16, __half, wmma::row_major> bf;
                wmma::load_matrix_sync(bf, &sB[k0 + kk][warp_n * 64 + ni * 16], OUT_F);
#pragma unroll
                for (int mi = 0; mi < 4; mi++)
                    wmma::mma_sync(acc[mi][ni], a[mi], bf, acc[mi][ni]);
            }
        }
        __syncthreads();
    }

    // epilogue: stage fp32 accs through smem (A region), emit fp16
    float* sE = reinterpret_cast<float*>(smem_raw + SB_BYTES) + wid * (16 * LDE_S);
#pragma unroll
    for (int mi = 0; mi < 4; mi++) {
#pragma unroll
        for (int ni = 0; ni < 4; ni++) {
            wmma::store_matrix_sync(sE, acc[mi][ni], LDE_S, wmma::mem_row_major);
            __syncwarp();
            const int r = lane >> 1;
            const int c0 = (lane & 1) * 8;
            const int row = block_row + warp_m * 64 + mi * 16 + r;
            if (row < M) {
                const float* s = sE + r * LDE_S + c0;
                __half2 hv[4];
                hv[0] = __floats2half2_rn(s[0], s[1]);
                hv[1] = __floats2half2_rn(s[2], s[3]);
                hv[2] = __floats2half2_rn(s[4], s[5]);
                hv[3] = __floats2half2_rn(s[6], s[7]);
                const int col = warp_n * 64 + ni * 16 + c0;
                *reinterpret_cast<float4*>(&g_h2[(size_t)row * (OUT_F / 2) + col / 2]) =
                    *reinterpret_cast<float4*>(hv);
            }
            __syncwarp();
        }
    }
}

// ---------------- 2) CSR build -----------------------------------------
__global__ void zero_counts_kernel(int n)
{
    int i = blockIdx.x * blockDim.x + threadIdx.x;
    if (i < n) g_counts[i] = 0;
}

__global__ void hist_kernel(const int* __restrict__ edst, int E, int n_nodes)
{
    int t = blockIdx.x * blockDim.x + threadIdx.x;
    int base = t * 4;
    if (base + 3 < E) {
        int4 d4 = *reinterpret_cast<const int4*>(edst + base);
        atomicAdd(&g_counts[clamp_idx(d4.x, n_nodes)], 1);
        atomicAdd(&g_counts[clamp_idx(d4.y, n_nodes)], 1);
        atomicAdd(&g_counts[clamp_idx(d4.z, n_nodes)], 1);
        atomicAdd(&g_counts[clamp_idx(d4.w, n_nodes)], 1);
    } else {
        for (int e = base; e < E; e++)
            atomicAdd(&g_counts[clamp_idx(edst[e], n_nodes)], 1);
    }
}

__global__ __launch_bounds__(1024) void scan_pass1(int n)
{
    __shared__ int warp_sums[32];
    const int tid = threadIdx.x;
    const int i = blockIdx.x * SCAN_CHUNK + tid;
    int v = (i < n) ? g_counts[i] : 0;
    int s = v;
#pragma unroll
    for (int off = 16; off > 0; off >>= 1) s += __shfl_down_sync(0xffffffffu, s, off);
    if ((tid & 31) == 0) warp_sums[tid >> 5] = s;
    __syncthreads();
    if (tid < 32) {
        int t = warp_sums[tid];
#pragma unroll
        for (int off = 16; off > 0; off >>= 1) t += __shfl_down_sync(0xffffffffu, t, off);
        if (tid == 0) g_blocksums[blockIdx.x] = t;
    }
}

__global__ __launch_bounds__(128) void scan_pass2(int nblocks)
{
    const int tid = threadIdx.x;
    int v = (tid < nblocks) ? g_blocksums[tid] : 0;
    int x = v;
#pragma unroll
    for (int off = 1; off < 32; off <<= 1) {
        int y = __shfl_up_sync(0xffffffffu, x, off);
        if ((tid & 31) >= off) x += y;
    }
    __shared__ int ws[4];
    if ((tid & 31) == 31) ws[tid >> 5] = x;
    __syncthreads();
    int add = 0;
    for (int wlt = 0; wlt < (tid >> 5); wlt++) add += ws[wlt];
    int incl = x + add;
    if (tid < nblocks) g_blockoffs[tid] = incl - v;
}

__global__ __launch_bounds__(1024) void scan_pass3(int n)
{
    __shared__ int warp_sums[32];
    const int tid = threadIdx.x;
    const int i = blockIdx.x * SCAN_CHUNK + tid;
    int v = (i < n) ? g_counts[i] : 0;
    int x = v;
#pragma unroll
    for (int off = 1; off < 32; off <<= 1) {
        int y = __shfl_up_sync(0xffffffffu, x, off);
        if ((tid & 31) >= off) x += y;
    }
    if ((tid & 31) == 31) warp_sums[tid >> 5] = x;
    __syncthreads();
    if (tid < 32) {
        int t = warp_sums[tid];
#pragma unroll
        for (int off = 1; off < 32; off <<= 1) {
            int y = __shfl_up_sync(0xffffffffu, t, off);
            if (tid >= off) t += y;
        }
        warp_sums[tid] = t;
    }
    __syncthreads();
    int warp_off = (tid >> 5) ? warp_sums[(tid >> 5) - 1] : 0;
    int excl = x - v + warp_off + g_blockoffs[blockIdx.x];
    if (i < n) {
        g_rowstart[i] = excl;
        g_cursor[i]   = excl;
    }
}

__global__ void fill_kernel(const int* __restrict__ esrc,
                            const int* __restrict__ edst,
                            const float* __restrict__ ew, int E, int n_nodes)
{
    int e = blockIdx.x * blockDim.x + threadIdx.x;
    if (e < E) {
        int d = clamp_idx(edst[e], n_nodes);
        int pos = atomicAdd(&g_cursor[d], 1);
        if (pos >= 0 && pos < N_EDGES_MAX) {
            g_sorted_src[pos] = clamp_idx(esrc[e], n_nodes);
            g_sorted_w[pos]   = ew[e];
        }
    }
}

// ------- 3) gather: warp/node, fp16 h rows (8B/lane/edge), unrolled x4 ------
__global__ __launch_bounds__(256) void gather_kernel(
    const float* __restrict__ b, float* __restrict__ out, int n_nodes)
{
    const int gtid = blockIdx.x * blockDim.x + threadIdx.x;
    const int node = gtid >> 5;
    const int lane = gtid & 31;
    if (node >= n_nodes) return;

    const int start = g_rowstart[node];
    const int cnt   = g_counts[node];
    const __half2* hbase = g_h2 + (size_t)lane * 2;

    float4 acc0 = make_float4(0.f, 0.f, 0.f, 0.f);
    float4 acc1 = make_float4(0.f, 0.f, 0.f, 0.f);

    int j = 0;
    for (; j + 4 <= cnt; j += 4) {
        const int   s0 = g_sorted_src[start + j + 0];
        const int   s1 = g_sorted_src[start + j + 1];
        const int   s2 = g_sorted_src[start + j + 2];
        const int   s3 = g_sorted_src[start + j + 3];
        const float w0 = g_sorted_w[start + j + 0];
        const float w1 = g_sorted_w[start + j + 1];
        const float w2 = g_sorted_w[start + j + 2];
        const float w3 = g_sorted_w[start + j + 3];
        const __half2* p0 = hbase + (size_t)s0 * (OUT_F / 2);
        const __half2* p1 = hbase + (size_t)s1 * (OUT_F / 2);
        const __half2* p2 = hbase + (size_t)s2 * (OUT_F / 2);
        const __half2* p3 = hbase + (size_t)s3 * (OUT_F / 2);
        float2 a, c;
        a = __half22float2(p0[0]); c = __half22float2(p0[1]);
        acc0.x += w0 * a.x; acc0.y += w0 * a.y; acc0.z += w0 * c.x; acc0.w += w0 * c.y;
        a = __half22float2(p1[0]); c = __half22float2(p1[1]);
        acc1.x += w1 * a.x; acc1.y += w1 * a.y; acc1.z += w1 * c.x; acc1.w += w1 * c.y;
        a = __half22float2(p2[0]); c = __half22float2(p2[1]);
        acc0.x += w2 * a.x; acc0.y += w2 * a.y; acc0.z += w2 * c.x; acc0.w += w2 * c.y;
        a = __half22float2(p3[0]); c = __half22float2(p3[1]);
        acc1.x += w3 * a.x; acc1.y += w3 * a.y; acc1.z += w3 * c.x; acc1.w += w3 * c.y;
    }
    for (; j < cnt; j++) {
        const int   s  = g_sorted_src[start + j];
        const float wt = g_sorted_w[start + j];
        const __half2* p = hbase + (size_t)s * (OUT_F / 2);
        float2 a = __half22float2(p[0]);
        float2 c = __half22float2(p[1]);
        acc0.x += wt * a.x; acc0.y += wt * a.y; acc0.z += wt * c.x; acc0.w += wt * c.y;
    }

    const float4 bb = reinterpret_cast<const float4*>(b)[lane];
    float4 r;
    r.x = acc0.x + acc1.x + bb.x;
    r.y = acc0.y + acc1.y + bb.y;
    r.z = acc0.z + acc1.z + bb.z;
    r.w = acc0.w + acc1.w + bb.w;
    reinterpret_cast<float4*>(out)[(size_t)node * 32 + lane] = r;
}

// ---------------------------- launch ---------------------------------------
extern "C" void kernel_launch(void* const* d_in, const int* in_sizes, int n_in,
                              void* d_out, int out_size)
{
    const float* x    = (const float*)d_in[0];
    const int*   esrc = (const int*)d_in[1];
    const int*   edst = (const int*)d_in[2];
    const float* ew   = (const float*)d_in[3];
    const float* w    = (const float*)d_in[4];
    const float* b    = (const float*)d_in[5];
    float*       out  = (float*)d_out;

    const int M = in_sizes[0] / IN_F;   // 100000
    const int E = in_sizes[1];          // 1600000
    const int nscan = (M + SCAN_CHUNK - 1) / SCAN_CHUNK;

    static cudaStream_t s_side = nullptr;
    static cudaEvent_t  e_fork = nullptr, e_join = nullptr;
    if (!s_side) {
        cudaStreamCreateWithFlags(&s_side, cudaStreamNonBlocking);
        cudaEventCreateWithFlags(&e_fork, cudaEventDisableTiming);
        cudaEventCreateWithFlags(&e_join, cudaEventDisableTiming);
        cudaFuncSetAttribute(gemm_wmma_kernel,
                             cudaFuncAttributeMaxDynamicSharedMemorySize, SMEM_RAW);
    }

    // launch order keeps gemm at index 3 so ncu (-s skip) profiles it
    prep_w_kernel<<<(IN_F * OUT_F + 255) / 256, 256>>>(w);        // 0 (main)

    cudaEventRecord(e_fork, 0);
    cudaStreamWaitEvent(s_side, e_fork, 0);

    zero_counts_kernel<<<(M + 255) / 256, 256, 0, s_side>>>(M);   // 1 (side)
    hist_kernel<<<((E + 3) / 4 + 255) / 256, 256, 0, s_side>>>(edst, E, M); // 2

    gemm_wmma_kernel<<<(M + GEMM_BM - 1) / GEMM_BM, 256, SMEM_RAW>>>(x, M); // 3 (main)

    scan_pass1<<<nscan, 1024, 0, s_side>>>(M);                    // 4
    scan_pass2<<<1, 128, 0, s_side>>>(nscan);                     // 5
    scan_pass3<<<nscan, 1024, 0, s_side>>>(M);                    // 6
    fill_kernel<<<(E + 255) / 256, 256, 0, s_side>>>(esrc, edst, ew, E, M); // 7

    cudaEventRecord(e_join, s_side);
    cudaStreamWaitEvent(0, e_join, 0);

    gather_kernel<<<((M * 32) + 255) / 256, 256>>>(b, out, M);    // 8
}